// round 8
// baseline (speedup 1.0000x reference)
#include <cuda_runtime.h>
#include <cuda_bf16.h>
#include <cstdint>
#include <cstddef>

#define PB 256
#define PT 1024
#define PD 128
#define PH 256
#define BT (PB * PT)   // 262144 tokens

// ---------------- scratch (device globals; no cudaMalloc allowed) ----------
__device__ float g_pA[2048 * 256];   // scan partials (fp32)
__device__ float g_pB[2048 * 256];

// padded, transposed ([N, K] K-major) bf16 weights
__device__ __nv_bfloat16 g_WxT[256 * 128];
__device__ __nv_bfloat16 g_W1T[128 * 128];
__device__ __nv_bfloat16 g_W2T[128 * 128];
__device__ __nv_bfloat16 g_W3T[128 * 128];
__device__ __nv_bfloat16 g_W4T[64 * 128];
__device__ __nv_bfloat16 g_W5T[256 * 64];
__device__ float g_b1p[128], g_b2p[128], g_b3p[128], g_b4p[64];

__device__ __forceinline__ float sigf(float x) { return 1.f / (1.f + __expf(-x)); }

__device__ __forceinline__ uint32_t smem_u32(const void* p) {
    uint32_t a;
    asm("{ .reg .u64 t; cvta.to.shared.u64 t, %1; cvt.u32.u64 %0, t; }" : "=r"(a) : "l"(p));
    return a;
}
__device__ __forceinline__ void cp16(uint32_t dst, const void* src) {
    asm volatile("cp.async.ca.shared.global [%0], [%1], 16;" :: "r"(dst), "l"(src) : "memory");
}
__device__ __forceinline__ void cp_commit() {
    asm volatile("cp.async.commit_group;" ::: "memory");
}
template <int N>
__device__ __forceinline__ void cp_wait() {
    asm volatile("cp.async.wait_group %0;" :: "n"(N) : "memory");
}
__device__ __forceinline__ void mma16(float* c, const uint32_t* a, uint32_t b0, uint32_t b1) {
    asm volatile(
        "mma.sync.aligned.m16n8k16.row.col.f32.bf16.bf16.f32 "
        "{%0,%1,%2,%3}, {%4,%5,%6,%7}, {%8,%9}, {%0,%1,%2,%3};"
        : "+f"(c[0]), "+f"(c[1]), "+f"(c[2]), "+f"(c[3])
        : "r"(a[0]), "r"(a[1]), "r"(a[2]), "r"(a[3]), "r"(b0), "r"(b1));
}
__device__ __forceinline__ uint32_t ldu32(const __nv_bfloat16* p) {
    return *(const uint32_t*)p;
}

// ---------------- weight prep: transpose + pad + bf16 ----------------------
__global__ void prep_kernel(const float* __restrict__ Wx,
                            const float* __restrict__ W1, const float* __restrict__ b1,
                            const float* __restrict__ W2, const float* __restrict__ b2,
                            const float* __restrict__ W3, const float* __restrict__ b3,
                            const float* __restrict__ W4, const float* __restrict__ b4,
                            const float* __restrict__ W5)
{
    int t = blockIdx.x * blockDim.x + threadIdx.x;
    int S = gridDim.x * blockDim.x;
    for (int i = t; i < 256 * 128; i += S) { int n = i >> 7, k = i & 127; g_WxT[i] = __float2bfloat16(Wx[k * 256 + n]); }
    for (int i = t; i < 128 * 128; i += S) { int n = i >> 7, k = i & 127; g_W1T[i] = __float2bfloat16((n < 100) ? W1[k * 100 + n] : 0.f); }
    for (int i = t; i < 128 * 128; i += S) { int n = i >> 7, k = i & 127; g_W2T[i] = __float2bfloat16((n < 100 && k < 100) ? W2[k * 100 + n] : 0.f); }
    for (int i = t; i < 128 * 128; i += S) { int n = i >> 7, k = i & 127; g_W3T[i] = __float2bfloat16((n < 100 && k < 100) ? W3[k * 100 + n] : 0.f); }
    for (int i = t; i < 64 * 128;  i += S) { int n = i >> 7, k = i & 127; g_W4T[i] = __float2bfloat16((n < 50 && k < 100) ? W4[k * 50 + n] : 0.f); }
    for (int i = t; i < 256 * 64;  i += S) { int n = i >> 6, k = i & 63;  g_W5T[i] = __float2bfloat16((k < 50) ? W5[k * 256 + n] : 0.f); }
    for (int i = t; i < 128; i += S) {
        g_b1p[i] = (i < 100) ? b1[i] : 0.f;
        g_b2p[i] = (i < 100) ? b2[i] : 0.f;
        g_b3p[i] = (i < 100) ? b3[i] : 0.f;
    }
    for (int i = t; i < 64; i += S) g_b4p[i] = (i < 50) ? b4[i] : 0.f;
}

// ---------------- fully fused tile kernel -----------------------------------
// One CTA = 128 tokens (batch b = tile>>3, timesteps [ (tile&7)*128, +128 )).
// x -> bf16 smem -> L1..L4 -> fx/lin halves -> gate (smem only) -> scan partials.
#define PITCH 136            // bf16 elements per smem row (136*2=272B, 68 words)
#define XB   0               // x tile bf16            (128 x PITCH)
#define PING 17408           // act buffer A
#define PONG 34816           // act buffer B
#define WB0  52224           // weight buffer 0
#define WB1  69632           // weight buffer 1
#define SMEM_ELEMS 87040
#define SMEM_BYTES (SMEM_ELEMS * 2)

__global__ void __launch_bounds__(512, 1)
fused_kernel(const float* __restrict__ x,
             const __nv_bfloat16* __restrict__ WxT, const float* __restrict__ bx,
             const __nv_bfloat16* __restrict__ W1T, const float* __restrict__ b1p,
             const __nv_bfloat16* __restrict__ W2T, const float* __restrict__ b2p,
             const __nv_bfloat16* __restrict__ W3T, const float* __restrict__ b3p,
             const __nv_bfloat16* __restrict__ W4T, const float* __restrict__ b4p,
             const __nv_bfloat16* __restrict__ W5T, const float* __restrict__ b5,
             float* __restrict__ pA, float* __restrict__ pB)
{
    extern __shared__ __nv_bfloat16 smb[];
    const uint32_t sbase = smem_u32(smb);
    const int tid = threadIdx.x;
    const int lane = tid & 31, wid = tid >> 5;
    const int gq = lane >> 2, tig = lane & 3;
    const int wm = wid & 3, wn = wid >> 2;      // 4x4 warp grid, 32x32 warp tiles
    const int tile = blockIdx.x;
    const size_t rowBase = (size_t)tile * 128;

    // ---- helpers -----------------------------------------------------------
    auto load_w = [&](const __nv_bfloat16* W, int rows, int cols, int off) {
        const int nseg = cols >> 3;
        for (int id = tid; id < rows * nseg; id += 512) {
            int r = id / nseg, sg = (id % nseg) * 8;
            cp16(sbase + (uint32_t)(off + r * PITCH + sg) * 2u, W + (size_t)r * cols + sg);
        }
        cp_commit();
    };
    auto zacc = [&](float a[2][4][4]) {
        #pragma unroll
        for (int mt = 0; mt < 2; mt++)
            #pragma unroll
            for (int nt = 0; nt < 4; nt++)
                #pragma unroll
                for (int j = 0; j < 4; j++) a[mt][nt][j] = 0.f;
    };
    auto gemm = [&](int aOff, int wOff, int K, float acc[2][4][4], bool active) {
        if (!active) return;
        for (int s = 0; s < (K >> 4); s++) {
            const int k0 = s * 16;
            uint32_t af[2][4];
            #pragma unroll
            for (int mt = 0; mt < 2; mt++) {
                const __nv_bfloat16* ap = smb + aOff + (wm * 32 + mt * 16 + gq) * PITCH + k0 + 2 * tig;
                af[mt][0] = ldu32(ap);
                af[mt][1] = ldu32(ap + 8 * PITCH);
                af[mt][2] = ldu32(ap + 8);
                af[mt][3] = ldu32(ap + 8 * PITCH + 8);
            }
            #pragma unroll
            for (int nt = 0; nt < 4; nt++) {
                const __nv_bfloat16* bp = smb + wOff + (wn * 32 + nt * 8 + gq) * PITCH + k0 + 2 * tig;
                uint32_t b0 = ldu32(bp);
                uint32_t b1 = ldu32(bp + 8);
                mma16(acc[0][nt], af[0], b0, b1);
                mma16(acc[1][nt], af[1], b0, b1);
            }
        }
    };
    auto store_relu = [&](int dstOff, float acc[2][4][4], const float* bias, bool active) {
        if (!active) return;
        #pragma unroll
        for (int mt = 0; mt < 2; mt++)
            #pragma unroll
            for (int nt = 0; nt < 4; nt++) {
                const int c = wn * 32 + nt * 8 + 2 * tig;
                const float q0 = __ldg(bias + c), q1 = __ldg(bias + c + 1);
                #pragma unroll
                for (int h = 0; h < 2; h++) {
                    const int r = wm * 32 + mt * 16 + gq + h * 8;
                    float v0 = fmaxf(acc[mt][nt][2 * h + 0] + q0, 0.f);
                    float v1 = fmaxf(acc[mt][nt][2 * h + 1] + q1, 0.f);
                    *(__nv_bfloat162*)(smb + dstOff + r * PITCH + c) = __floats2bfloat162_rn(v0, v1);
                }
            }
    };
    auto store_gate = [&](int dstOff, float fxa[2][4][4], float lina[2][4][4], int hb) {
        #pragma unroll
        for (int mt = 0; mt < 2; mt++)
            #pragma unroll
            for (int nt = 0; nt < 4; nt++) {
                const int cl = wn * 32 + nt * 8 + 2 * tig;
                const int cg = hb * 128 + cl;
                const float q50 = __ldg(b5 + cg), q51 = __ldg(b5 + cg + 1);
                const float qx0 = __ldg(bx + cg), qx1 = __ldg(bx + cg + 1);
                #pragma unroll
                for (int h = 0; h < 2; h++) {
                    const int r = wm * 32 + mt * 16 + gq + h * 8;
                    float v0 = sigf(fxa[mt][nt][2 * h + 0] + q50) * sigf(lina[mt][nt][2 * h + 0] + qx0);
                    float v1 = sigf(fxa[mt][nt][2 * h + 1] + q51) * sigf(lina[mt][nt][2 * h + 1] + qx1);
                    *(__nv_bfloat162*)(smb + dstOff + r * PITCH + cl) = __floats2bfloat162_rn(v0, v1);
                }
            }
    };

    float acc[2][4][4], acc2[2][4][4];

    // ---- prologue: W1 prefetch + x load/convert ---------------------------
    load_w(W1T, 128, 128, WB0);                       // group 0
    for (int id = tid; id < 4096; id += 512) {
        int r = id >> 5, c4 = (id & 31) * 4;
        float4 v = __ldg((const float4*)(x + (rowBase + r) * 128 + c4));
        *(__nv_bfloat162*)(smb + XB + r * PITCH + c4)     = __floats2bfloat162_rn(v.x, v.y);
        *(__nv_bfloat162*)(smb + XB + r * PITCH + c4 + 2) = __floats2bfloat162_rn(v.z, v.w);
    }
    load_w(W2T, 128, 128, WB1);                       // group 1

    // ---- L1: PING = relu(XB @ W1) -----------------------------------------
    cp_wait<1>(); __syncthreads();                    // W1 done + XB visible
    zacc(acc); gemm(XB, WB0, 128, acc, true);
    store_relu(PING, acc, b1p, true);
    __syncthreads();
    load_w(W3T, 128, 128, WB0);                       // group 2

    // ---- L2: PONG = relu(PING @ W2) ---------------------------------------
    cp_wait<1>(); __syncthreads();
    zacc(acc); gemm(PING, WB1, 128, acc, true);
    store_relu(PONG, acc, b2p, true);
    __syncthreads();
    load_w(W4T, 64, 128, WB1);                        // group 3

    // ---- L3: PING = relu(PONG @ W3) ---------------------------------------
    cp_wait<1>(); __syncthreads();
    zacc(acc); gemm(PONG, WB0, 128, acc, true);
    store_relu(PING, acc, b3p, true);
    __syncthreads();
    load_w(W5T, 128, 64, WB0);                        // group 4 (W5 half 0)

    // ---- L4: PONG[:, :64] = relu(PING @ W4), warps wn<2 only --------------
    cp_wait<1>(); __syncthreads();
    zacc(acc); gemm(PING, WB1, 128, acc, wn < 2);
    store_relu(PONG, acc, b4p, wn < 2);
    __syncthreads();
    load_w(WxT, 128, 128, WB1);                       // group 5 (Wx half 0)

    // ---- fx half 0: acc = PONG(a4) @ W5h0  (K=64) -------------------------
    cp_wait<1>(); __syncthreads();
    zacc(acc); gemm(PONG, WB0, 64, acc, true);
    __syncthreads();                                  // WB0 free
    load_w(W5T + 128 * 64, 128, 64, WB0);             // group 6 (W5 half 1)

    // ---- lin half 0: acc2 = XB @ Wxh0 (K=128); gate h0 -> PING ------------
    cp_wait<1>(); __syncthreads();
    zacc(acc2); gemm(XB, WB1, 128, acc2, true);
    store_gate(PING, acc, acc2, 0);                   // PING free since L4
    __syncthreads();                                  // WB1 free + gate h0 visible
    load_w(WxT + 128 * 128, 128, 128, WB1);           // group 7 (Wx half 1)

    // ---- fx half 1 (reads PONG a4), lin half 1; gate h1 -> PONG -----------
    cp_wait<1>(); __syncthreads();
    zacc(acc); gemm(PONG, WB0, 64, acc, true);
    cp_wait<0>(); __syncthreads();                    // Wx h1 ready
    zacc(acc2); gemm(XB, WB1, 128, acc2, true);
    __syncthreads();                                  // all PONG(a4) reads done
    store_gate(PONG, acc, acc2, 1);
    __syncthreads();                                  // gate tile complete

    // ---- in-tile scan partials (max-plus) ---------------------------------
    // per hidden coord i, local steps t: col = (i + t0 + 1 + t) & 255.
    // gate cols 0-127 in PING, 128-255 in PONG.
    {
        const int i = tid & 255, sub = tid >> 8;
        const int t0 = (tile & 7) * 128;
        float As = 0.f, Bs = -3.0e38f;
        int col = (i + t0 + 1 + sub * 64) & 255;
        #pragma unroll 4
        for (int j = 0; j < 64; j++) {
            const int t = sub * 64 + j;
            const __nv_bfloat16* bufp = (col & 128) ? (smb + PONG) : (smb + PING);
            float val = __bfloat162float(bufp[t * PITCH + (col & 127)]);
            As += val;
            Bs = fmaxf(Bs + val, 0.f);
            col = (col + 1) & 255;
        }
        float* ex = (float*)smb;                       // XB region is free now
        if (sub == 1) { ex[i] = As; ex[256 + i] = Bs; }
        __syncthreads();
        if (sub == 0) {
            const float A1 = ex[i], B1 = ex[256 + i];
            const size_t o = (size_t)tile * 256 + i;
            pA[o] = As + A1;
            pB[o] = fmaxf(Bs + A1, B1);
        }
    }
}

// ---------------- final combine + output head ------------------------------
__global__ void __launch_bounds__(256)
scan_fin(const float* __restrict__ pA, const float* __restrict__ pB,
         const float* __restrict__ Wo, const float* __restrict__ bo,
         float* __restrict__ out)
{
    const int b = blockIdx.x, i = threadIdx.x;
    float A = 0.f, B = -3.0e38f;
    #pragma unroll
    for (int c = 0; c < 8; c++) {
        const int o = (b * 8 + c) * 256 + i;
        float Ac = pA[o], Bc = pB[o];
        B = fmaxf(B + Ac, Bc);
        A += Ac;
    }
    const float v = fmaxf(A, B);    // apply to h0 = 0
    out[PB + (size_t)b * 256 + i] = v;

    __shared__ float sh[256];
    sh[i] = v * Wo[i];
    __syncthreads();
    #pragma unroll
    for (int s = 128; s > 0; s >>= 1) {
        if (i < s) sh[i] += sh[i + s];
        __syncthreads();
    }
    if (i == 0) out[b] = 1.f / (1.f + __expf(-(sh[0] + bo[0])));
}

// ---------------- launch ---------------------------------------------------
extern "C" void kernel_launch(void* const* d_in, const int* in_sizes, int n_in,
                              void* d_out, int out_size)
{
    const float* x  = (const float*)d_in[0];
    const float* Wx = (const float*)d_in[1];
    const float* bx = (const float*)d_in[2];
    const float* W1 = (const float*)d_in[3];
    const float* b1 = (const float*)d_in[4];
    const float* W2 = (const float*)d_in[5];
    const float* b2 = (const float*)d_in[6];
    const float* W3 = (const float*)d_in[7];
    const float* b3 = (const float*)d_in[8];
    const float* W4 = (const float*)d_in[9];
    const float* b4 = (const float*)d_in[10];
    const float* W5 = (const float*)d_in[11];
    const float* b5 = (const float*)d_in[12];
    const float* Wo = (const float*)d_in[13];
    const float* bo = (const float*)d_in[14];
    float* out = (float*)d_out;

    void *p_pA, *p_pB;
    void *p_WxT, *p_W1T, *p_W2T, *p_W3T, *p_W4T, *p_W5T;
    void *p_b1p, *p_b2p, *p_b3p, *p_b4p;
    cudaGetSymbolAddress(&p_pA, g_pA);
    cudaGetSymbolAddress(&p_pB, g_pB);
    cudaGetSymbolAddress(&p_WxT, g_WxT);
    cudaGetSymbolAddress(&p_W1T, g_W1T);
    cudaGetSymbolAddress(&p_W2T, g_W2T);
    cudaGetSymbolAddress(&p_W3T, g_W3T);
    cudaGetSymbolAddress(&p_W4T, g_W4T);
    cudaGetSymbolAddress(&p_W5T, g_W5T);
    cudaGetSymbolAddress(&p_b1p, g_b1p);
    cudaGetSymbolAddress(&p_b2p, g_b2p);
    cudaGetSymbolAddress(&p_b3p, g_b3p);
    cudaGetSymbolAddress(&p_b4p, g_b4p);

    cudaFuncSetAttribute(fused_kernel, cudaFuncAttributeMaxDynamicSharedMemorySize, SMEM_BYTES);

    prep_kernel<<<128, 256>>>(Wx, W1, b1, W2, b2, W3, b3, W4, b4, W5);

    fused_kernel<<<BT / 128, 512, SMEM_BYTES>>>(
        x,
        (const __nv_bfloat16*)p_WxT, bx,
        (const __nv_bfloat16*)p_W1T, (const float*)p_b1p,
        (const __nv_bfloat16*)p_W2T, (const float*)p_b2p,
        (const __nv_bfloat16*)p_W3T, (const float*)p_b3p,
        (const __nv_bfloat16*)p_W4T, (const float*)p_b4p,
        (const __nv_bfloat16*)p_W5T, b5,
        (float*)p_pA, (float*)p_pB);

    scan_fin<<<PB, 256>>>((const float*)p_pA, (const float*)p_pB, Wo, bo, out);
}

// round 9
// speedup vs baseline: 1.4623x; 1.4623x over previous
#include <cuda_runtime.h>
#include <cuda_bf16.h>
#include <cstdint>
#include <cstddef>

#define PB 256
#define PT 1024
#define PD 128
#define PH 256
#define BT (PB * PT)   // 262144 tokens
#define MTILES (BT / 128)  // 2048

// ---------------- scratch (device globals; no cudaMalloc allowed) ----------
__device__ __nv_bfloat16 g_gate[(size_t)BT * PH];  // gate bf16 (128 MB)
__device__ __nv_bfloat16 g_xb[(size_t)BT * 128];   // x in bf16
__device__ __nv_bfloat16 g_a[(size_t)BT * 128];    // MLP ping (padded)
__device__ __nv_bfloat16 g_b[(size_t)BT * 128];    // MLP pong
__device__ __nv_bfloat16 g_c[(size_t)BT * 64];     // layer-4 out (padded)
__device__ float g_pA[2048 * 256];                 // scan partials (fp32)
__device__ float g_pB[2048 * 256];

// padded, transposed ([N, K] K-major) bf16 weights
__device__ __nv_bfloat16 g_WxT[256 * 128];
__device__ __nv_bfloat16 g_W1T[128 * 128];
__device__ __nv_bfloat16 g_W2T[128 * 128];
__device__ __nv_bfloat16 g_W3T[128 * 128];
__device__ __nv_bfloat16 g_W4T[64 * 128];
__device__ __nv_bfloat16 g_W5T[256 * 64];
__device__ float g_b1p[128], g_b2p[128], g_b3p[128], g_b4p[64];

__device__ __forceinline__ float sigf(float x) { return 1.f / (1.f + __expf(-x)); }

__device__ __forceinline__ uint32_t smem_u32(const void* p) {
    uint32_t a;
    asm("{ .reg .u64 t; cvta.to.shared.u64 t, %1; cvt.u32.u64 %0, t; }" : "=r"(a) : "l"(p));
    return a;
}
__device__ __forceinline__ void cp16(uint32_t dst, const void* src) {
    asm volatile("cp.async.ca.shared.global [%0], [%1], 16;" :: "r"(dst), "l"(src) : "memory");
}
__device__ __forceinline__ void cp_commit() {
    asm volatile("cp.async.commit_group;" ::: "memory");
}
template <int N>
__device__ __forceinline__ void cp_wait() {
    asm volatile("cp.async.wait_group %0;" :: "n"(N) : "memory");
}
__device__ __forceinline__ void mma16(float* c, const uint32_t* a, uint32_t b0, uint32_t b1) {
    asm volatile(
        "mma.sync.aligned.m16n8k16.row.col.f32.bf16.bf16.f32 "
        "{%0,%1,%2,%3}, {%4,%5,%6,%7}, {%8,%9}, {%0,%1,%2,%3};"
        : "+f"(c[0]), "+f"(c[1]), "+f"(c[2]), "+f"(c[3])
        : "r"(a[0]), "r"(a[1]), "r"(a[2]), "r"(a[3]), "r"(b0), "r"(b1));
}
__device__ __forceinline__ uint32_t ldu32(const __nv_bfloat16* p) {
    return *(const uint32_t*)p;
}

// ---------------- weight prep: transpose + pad + bf16 ----------------------
__global__ void prep_kernel(const float* __restrict__ Wx,
                            const float* __restrict__ W1, const float* __restrict__ b1,
                            const float* __restrict__ W2, const float* __restrict__ b2,
                            const float* __restrict__ W3, const float* __restrict__ b3,
                            const float* __restrict__ W4, const float* __restrict__ b4,
                            const float* __restrict__ W5)
{
    int t = blockIdx.x * blockDim.x + threadIdx.x;
    int S = gridDim.x * blockDim.x;
    for (int i = t; i < 256 * 128; i += S) { int n = i >> 7, k = i & 127; g_WxT[i] = __float2bfloat16(Wx[k * 256 + n]); }
    for (int i = t; i < 128 * 128; i += S) { int n = i >> 7, k = i & 127; g_W1T[i] = __float2bfloat16((n < 100) ? W1[k * 100 + n] : 0.f); }
    for (int i = t; i < 128 * 128; i += S) { int n = i >> 7, k = i & 127; g_W2T[i] = __float2bfloat16((n < 100 && k < 100) ? W2[k * 100 + n] : 0.f); }
    for (int i = t; i < 128 * 128; i += S) { int n = i >> 7, k = i & 127; g_W3T[i] = __float2bfloat16((n < 100 && k < 100) ? W3[k * 100 + n] : 0.f); }
    for (int i = t; i < 64 * 128;  i += S) { int n = i >> 7, k = i & 127; g_W4T[i] = __float2bfloat16((n < 50 && k < 100) ? W4[k * 50 + n] : 0.f); }
    for (int i = t; i < 256 * 64;  i += S) { int n = i >> 6, k = i & 63;  g_W5T[i] = __float2bfloat16((k < 50) ? W5[k * 256 + n] : 0.f); }
    for (int i = t; i < 128; i += S) {
        g_b1p[i] = (i < 100) ? b1[i] : 0.f;
        g_b2p[i] = (i < 100) ? b2[i] : 0.f;
        g_b3p[i] = (i < 100) ? b3[i] : 0.f;
    }
    for (int i = t; i < 64; i += S) g_b4p[i] = (i < 50) ? b4[i] : 0.f;
}

// ---------------- x -> bf16 -------------------------------------------------
__global__ void __launch_bounds__(256)
conv_x(const float* __restrict__ x, __nv_bfloat16* __restrict__ xb)
{
    size_t i = ((size_t)blockIdx.x * 256 + threadIdx.x) * 4;
    float4 v = *(const float4*)(x + i);
    __nv_bfloat162* o = (__nv_bfloat162*)(xb + i);
    o[0] = __floats2bfloat162_rn(v.x, v.y);
    o[1] = __floats2bfloat162_rn(v.z, v.w);
}

// ---------------- persistent bf16 GEMM (relu) -------------------------------
// Weights resident in SMEM; CTA loops M-tiles with 2-stage cp.async A buffer.
// C[tile 128, BN] = relu(A[128, K] @ Bw[N, K]^T + bias)
template <int K, int NFULL, int BN>
__global__ void __launch_bounds__(256, 2)
pgemm(const __nv_bfloat16* __restrict__ A, const __nv_bfloat16* __restrict__ Bw,
      const float* __restrict__ bias, __nv_bfloat16* __restrict__ C)
{
    constexpr int PITCH = K + 8;
    constexpr int WELEM = BN * PITCH;
    constexpr int ASTAGE = 128 * PITCH;
    constexpr int WN = BN / 2;
    constexpr int NT = WN / 8;
    extern __shared__ __nv_bfloat16 smb[];
    const uint32_t sbase = smem_u32(smb);

    const int tid = threadIdx.x;
    const int lane = tid & 31, wid = tid >> 5;
    const int gq = lane >> 2, tig = lane & 3;
    const int wm = wid & 3, wn = wid >> 2;
    const int colBase = blockIdx.x * BN;
    const int t0 = blockIdx.y, stride = gridDim.y;

    // resident weights (group 0)
    for (int id = tid; id < BN * (K / 8); id += 256) {
        int r = id / (K / 8), sg = (id % (K / 8)) * 8;
        cp16(sbase + (uint32_t)(r * PITCH + sg) * 2u, Bw + (size_t)(colBase + r) * K + sg);
    }
    cp_commit();

    auto loadA = [&](int tile, int buf) {
        if (tile < MTILES) {
            const size_t rb = (size_t)tile * 128;
            #pragma unroll
            for (int it = 0; it < (K / 8) * 128 / 256; it++) {
                int id = tid + it * 256;
                int r = id / (K / 8), sg = (id % (K / 8)) * 8;
                cp16(sbase + (uint32_t)(WELEM + buf * ASTAGE + r * PITCH + sg) * 2u,
                     A + (rb + r) * K + sg);
            }
        }
        cp_commit();
    };
    loadA(t0, 0);
    loadA(t0 + stride, 1);

    // hoisted bias
    float bs[NT][2];
    #pragma unroll
    for (int nt = 0; nt < NT; nt++) {
        const int c0 = colBase + wn * WN + nt * 8 + 2 * tig;
        bs[nt][0] = __ldg(bias + c0);
        bs[nt][1] = __ldg(bias + c0 + 1);
    }

    for (int t = t0, it = 0; t < MTILES; t += stride, it++) {
        cp_wait<1>();
        __syncthreads();
        const __nv_bfloat16* As = smb + WELEM + (it & 1) * ASTAGE;

        float acc[2][NT][4];
        #pragma unroll
        for (int mt = 0; mt < 2; mt++)
            #pragma unroll
            for (int nt = 0; nt < NT; nt++)
                #pragma unroll
                for (int j = 0; j < 4; j++) acc[mt][nt][j] = 0.f;

        #pragma unroll
        for (int s = 0; s < K / 16; s++) {
            const int k0 = s * 16;
            uint32_t af[2][4];
            #pragma unroll
            for (int mt = 0; mt < 2; mt++) {
                const __nv_bfloat16* ap = As + (wm * 32 + mt * 16 + gq) * PITCH + k0 + 2 * tig;
                af[mt][0] = ldu32(ap);
                af[mt][1] = ldu32(ap + 8 * PITCH);
                af[mt][2] = ldu32(ap + 8);
                af[mt][3] = ldu32(ap + 8 * PITCH + 8);
            }
            #pragma unroll
            for (int nt = 0; nt < NT; nt++) {
                const __nv_bfloat16* bp = smb + (wn * WN + nt * 8 + gq) * PITCH + k0 + 2 * tig;
                uint32_t b0 = ldu32(bp);
                uint32_t b1 = ldu32(bp + 8);
                mma16(acc[0][nt], af[0], b0, b1);
                mma16(acc[1][nt], af[1], b0, b1);
            }
        }
        __syncthreads();
        loadA(t + 2 * stride, it & 1);   // prefetch overlaps epilogue

        const size_t rowBase = (size_t)t * 128;
        #pragma unroll
        for (int mt = 0; mt < 2; mt++)
            #pragma unroll
            for (int nt = 0; nt < NT; nt++) {
                const int c0 = colBase + wn * WN + nt * 8 + 2 * tig;
                #pragma unroll
                for (int h = 0; h < 2; h++) {
                    const size_t r = rowBase + wm * 32 + mt * 16 + gq + h * 8;
                    float v0 = fmaxf(acc[mt][nt][2 * h + 0] + bs[nt][0], 0.f);
                    float v1 = fmaxf(acc[mt][nt][2 * h + 1] + bs[nt][1], 0.f);
                    *(__nv_bfloat162*)(C + r * NFULL + c0) = __floats2bfloat162_rn(v0, v1);
                }
            }
    }
}

// ---------------- persistent fused gate GEMM --------------------------------
// gate[:, half*128 + 0..127] = sigmoid(vc@W5h + b5) * sigmoid(xb@Wxh + bx)
// Wx/W5 column-halves resident; xb+vc tiles double-buffered. 512 thr, 16 warps.
__global__ void __launch_bounds__(512, 1)
pgate(const __nv_bfloat16* __restrict__ xb, const __nv_bfloat16* __restrict__ WxT,
      const float* __restrict__ bx,
      const __nv_bfloat16* __restrict__ vc, const __nv_bfloat16* __restrict__ W5T,
      const float* __restrict__ b5, __nv_bfloat16* __restrict__ C)
{
    constexpr int PX = 136, PV = 72;
    constexpr int WX = 0;                 // Wx half: 128 x PX
    constexpr int W5 = 128 * PX;          // W5 half: 128 x PV
    constexpr int XB0 = W5 + 128 * PV;    // xb stages
    constexpr int XB1 = XB0 + 128 * PX;
    constexpr int VC0 = XB1 + 128 * PX;   // vc stages
    constexpr int VC1 = VC0 + 128 * PV;
    extern __shared__ __nv_bfloat16 smb[];
    const uint32_t sbase = smem_u32(smb);

    const int tid = threadIdx.x;
    const int lane = tid & 31, wid = tid >> 5;
    const int gq = lane >> 2, tig = lane & 3;
    const int wm = wid & 3, wn = wid >> 2;      // 4x4 warps, 32x32 tiles
    const int half = blockIdx.x;
    const int t0 = blockIdx.y, stride = gridDim.y;

    // resident weight halves (groups 0,1)
    for (int id = tid; id < 128 * 16; id += 512) {
        int r = id >> 4, sg = (id & 15) * 8;
        cp16(sbase + (uint32_t)(WX + r * PX + sg) * 2u,
             WxT + (size_t)(half * 128 + r) * 128 + sg);
    }
    cp_commit();
    for (int id = tid; id < 128 * 8; id += 512) {
        int r = id >> 3, sg = (id & 7) * 8;
        cp16(sbase + (uint32_t)(W5 + r * PV + sg) * 2u,
             W5T + (size_t)(half * 128 + r) * 64 + sg);
    }
    cp_commit();

    auto load_stage = [&](int tile, int buf) {
        if (tile < MTILES) {
            const size_t rb = (size_t)tile * 128;
            const int xoff = buf ? XB1 : XB0;
            const int voff = buf ? VC1 : VC0;
            #pragma unroll
            for (int it = 0; it < 4; it++) {
                int id = tid + it * 512;
                int r = id >> 4, sg = (id & 15) * 8;
                cp16(sbase + (uint32_t)(xoff + r * PX + sg) * 2u, xb + (rb + r) * 128 + sg);
            }
            #pragma unroll
            for (int it = 0; it < 2; it++) {
                int id = tid + it * 512;
                int r = id >> 3, sg = (id & 7) * 8;
                cp16(sbase + (uint32_t)(voff + r * PV + sg) * 2u, vc + (rb + r) * 64 + sg);
            }
        }
        cp_commit();
    };
    load_stage(t0, 0);
    load_stage(t0 + stride, 1);

    // hoisted biases
    float hbx[4][2], hb5[4][2];
    #pragma unroll
    for (int nt = 0; nt < 4; nt++) {
        const int cg = half * 128 + wn * 32 + nt * 8 + 2 * tig;
        hbx[nt][0] = __ldg(bx + cg); hbx[nt][1] = __ldg(bx + cg + 1);
        hb5[nt][0] = __ldg(b5 + cg); hb5[nt][1] = __ldg(b5 + cg + 1);
    }

    for (int t = t0, it = 0; t < MTILES; t += stride, it++) {
        cp_wait<1>();
        __syncthreads();
        const __nv_bfloat16* Xs = smb + (it & 1 ? XB1 : XB0);
        const __nv_bfloat16* Vs = smb + (it & 1 ? VC1 : VC0);

        float lin[2][4][4], fx[2][4][4];
        #pragma unroll
        for (int mt = 0; mt < 2; mt++)
            #pragma unroll
            for (int nt = 0; nt < 4; nt++)
                #pragma unroll
                for (int j = 0; j < 4; j++) { lin[mt][nt][j] = 0.f; fx[mt][nt][j] = 0.f; }

        // lin = Xs @ Wx_half (K=128)
        #pragma unroll
        for (int s = 0; s < 8; s++) {
            const int k0 = s * 16;
            uint32_t af[2][4];
            #pragma unroll
            for (int mt = 0; mt < 2; mt++) {
                const __nv_bfloat16* ap = Xs + (wm * 32 + mt * 16 + gq) * PX + k0 + 2 * tig;
                af[mt][0] = ldu32(ap);
                af[mt][1] = ldu32(ap + 8 * PX);
                af[mt][2] = ldu32(ap + 8);
                af[mt][3] = ldu32(ap + 8 * PX + 8);
            }
            #pragma unroll
            for (int nt = 0; nt < 4; nt++) {
                const __nv_bfloat16* bp = smb + WX + (wn * 32 + nt * 8 + gq) * PX + k0 + 2 * tig;
                uint32_t b0 = ldu32(bp);
                uint32_t b1 = ldu32(bp + 8);
                mma16(lin[0][nt], af[0], b0, b1);
                mma16(lin[1][nt], af[1], b0, b1);
            }
        }
        // fx = Vs @ W5_half (K=64)
        #pragma unroll
        for (int s = 0; s < 4; s++) {
            const int k0 = s * 16;
            uint32_t af[2][4];
            #pragma unroll
            for (int mt = 0; mt < 2; mt++) {
                const __nv_bfloat16* ap = Vs + (wm * 32 + mt * 16 + gq) * PV + k0 + 2 * tig;
                af[mt][0] = ldu32(ap);
                af[mt][1] = ldu32(ap + 8 * PV);
                af[mt][2] = ldu32(ap + 8);
                af[mt][3] = ldu32(ap + 8 * PV + 8);
            }
            #pragma unroll
            for (int nt = 0; nt < 4; nt++) {
                const __nv_bfloat16* bp = smb + W5 + (wn * 32 + nt * 8 + gq) * PV + k0 + 2 * tig;
                uint32_t b0 = ldu32(bp);
                uint32_t b1 = ldu32(bp + 8);
                mma16(fx[0][nt], af[0], b0, b1);
                mma16(fx[1][nt], af[1], b0, b1);
            }
        }
        __syncthreads();
        load_stage(t + 2 * stride, it & 1);   // prefetch overlaps epilogue

        const size_t rowBase = (size_t)t * 128;
        #pragma unroll
        for (int mt = 0; mt < 2; mt++)
            #pragma unroll
            for (int nt = 0; nt < 4; nt++) {
                const int cg = half * 128 + wn * 32 + nt * 8 + 2 * tig;
                #pragma unroll
                for (int h = 0; h < 2; h++) {
                    const size_t r = rowBase + wm * 32 + mt * 16 + gq + h * 8;
                    float v0 = sigf(fx[mt][nt][2 * h + 0] + hb5[nt][0]) * sigf(lin[mt][nt][2 * h + 0] + hbx[nt][0]);
                    float v1 = sigf(fx[mt][nt][2 * h + 1] + hb5[nt][1]) * sigf(lin[mt][nt][2 * h + 1] + hbx[nt][1]);
                    *(__nv_bfloat162*)(C + r * PH + cg) = __floats2bfloat162_rn(v0, v1);
                }
            }
    }
}

// ---------------- scan as max-plus reduction --------------------------------
__global__ void __launch_bounds__(256)
scan_part(const __nv_bfloat16* __restrict__ gate, float* __restrict__ pA, float* __restrict__ pB)
{
    const int b = blockIdx.x >> 3, c = blockIdx.x & 7;
    const int i = threadIdx.x;
    const __nv_bfloat16* gb = gate + ((size_t)b << 18);
    float Aacc = 0.f, Bacc = -3.0e38f;
    const int t0 = c * 128;
    #pragma unroll 8
    for (int t = t0; t < t0 + 128; t++) {
        float val = __bfloat162float(gb[(size_t)t * 256 + ((i + t + 1) & 255)]);
        Aacc += val;
        Bacc = fmaxf(Bacc + val, 0.f);
    }
    const int o = blockIdx.x * 256 + i;
    pA[o] = Aacc;
    pB[o] = Bacc;
}

__global__ void __launch_bounds__(256)
scan_fin(const float* __restrict__ pA, const float* __restrict__ pB,
         const float* __restrict__ Wo, const float* __restrict__ bo,
         float* __restrict__ out)
{
    const int b = blockIdx.x, i = threadIdx.x;
    float A = 0.f, B = -3.0e38f;
    #pragma unroll
    for (int c = 0; c < 8; c++) {
        const int o = (b * 8 + c) * 256 + i;
        float Ac = pA[o], Bc = pB[o];
        B = fmaxf(B + Ac, Bc);
        A += Ac;
    }
    const float v = fmaxf(A, B);
    out[PB + (size_t)b * 256 + i] = v;

    __shared__ float sh[256];
    sh[i] = v * Wo[i];
    __syncthreads();
    #pragma unroll
    for (int s = 128; s > 0; s >>= 1) {
        if (i < s) sh[i] += sh[i + s];
        __syncthreads();
    }
    if (i == 0) out[b] = 1.f / (1.f + __expf(-(sh[0] + bo[0])));
}

// ---------------- launch ---------------------------------------------------
extern "C" void kernel_launch(void* const* d_in, const int* in_sizes, int n_in,
                              void* d_out, int out_size)
{
    const float* x  = (const float*)d_in[0];
    const float* Wx = (const float*)d_in[1];
    const float* bx = (const float*)d_in[2];
    const float* W1 = (const float*)d_in[3];
    const float* b1 = (const float*)d_in[4];
    const float* W2 = (const float*)d_in[5];
    const float* b2 = (const float*)d_in[6];
    const float* W3 = (const float*)d_in[7];
    const float* b3 = (const float*)d_in[8];
    const float* W4 = (const float*)d_in[9];
    const float* b4 = (const float*)d_in[10];
    const float* W5 = (const float*)d_in[11];
    const float* b5 = (const float*)d_in[12];
    const float* Wo = (const float*)d_in[13];
    const float* bo = (const float*)d_in[14];
    float* out = (float*)d_out;

    void *p_gate, *p_xb, *p_a, *p_b, *p_c, *p_pA, *p_pB;
    void *p_WxT, *p_W1T, *p_W2T, *p_W3T, *p_W4T, *p_W5T;
    void *p_b1p, *p_b2p, *p_b3p, *p_b4p;
    cudaGetSymbolAddress(&p_gate, g_gate);
    cudaGetSymbolAddress(&p_xb, g_xb);
    cudaGetSymbolAddress(&p_a, g_a);
    cudaGetSymbolAddress(&p_b, g_b);
    cudaGetSymbolAddress(&p_c, g_c);
    cudaGetSymbolAddress(&p_pA, g_pA);
    cudaGetSymbolAddress(&p_pB, g_pB);
    cudaGetSymbolAddress(&p_WxT, g_WxT);
    cudaGetSymbolAddress(&p_W1T, g_W1T);
    cudaGetSymbolAddress(&p_W2T, g_W2T);
    cudaGetSymbolAddress(&p_W3T, g_W3T);
    cudaGetSymbolAddress(&p_W4T, g_W4T);
    cudaGetSymbolAddress(&p_W5T, g_W5T);
    cudaGetSymbolAddress(&p_b1p, g_b1p);
    cudaGetSymbolAddress(&p_b2p, g_b2p);
    cudaGetSymbolAddress(&p_b3p, g_b3p);
    cudaGetSymbolAddress(&p_b4p, g_b4p);
    __nv_bfloat16* gate = (__nv_bfloat16*)p_gate;
    __nv_bfloat16* xb   = (__nv_bfloat16*)p_xb;
    __nv_bfloat16* va   = (__nv_bfloat16*)p_a;
    __nv_bfloat16* vb   = (__nv_bfloat16*)p_b;
    __nv_bfloat16* vc   = (__nv_bfloat16*)p_c;

    // smem sizes (bytes)
    constexpr int S_P128 = (128 * 136 + 2 * 128 * 136) * 2;           // 104448
    constexpr int S_P64  = (64 * 136 + 2 * 128 * 136) * 2;            // 87040
    constexpr int S_GATE = (128 * 136 + 128 * 72 + 2 * 128 * 136 + 2 * 128 * 72) * 2;  // 159744
    cudaFuncSetAttribute(pgemm<128, 128, 128>, cudaFuncAttributeMaxDynamicSharedMemorySize, S_P128);
    cudaFuncSetAttribute(pgemm<128, 64, 64>,   cudaFuncAttributeMaxDynamicSharedMemorySize, S_P64);
    cudaFuncSetAttribute(pgate, cudaFuncAttributeMaxDynamicSharedMemorySize, S_GATE);

    prep_kernel<<<128, 256>>>(Wx, W1, b1, W2, b2, W3, b3, W4, b4, W5);
    conv_x<<<BT * 128 / (256 * 4), 256>>>(x, xb);

    // persistent MLP chain
    pgemm<128, 128, 128><<<dim3(1, 296), 256, S_P128>>>(xb, (const __nv_bfloat16*)p_W1T, (const float*)p_b1p, va);
    pgemm<128, 128, 128><<<dim3(1, 296), 256, S_P128>>>(va, (const __nv_bfloat16*)p_W2T, (const float*)p_b2p, vb);
    pgemm<128, 128, 128><<<dim3(1, 296), 256, S_P128>>>(vb, (const __nv_bfloat16*)p_W3T, (const float*)p_b3p, va);
    pgemm<128, 64, 64><<<dim3(1, 296), 256, S_P64>>>(va, (const __nv_bfloat16*)p_W4T, (const float*)p_b4p, vc);
    // persistent fused gate
    pgate<<<dim3(2, 74), 512, S_GATE>>>(xb, (const __nv_bfloat16*)p_WxT, bx,
                                        vc, (const __nv_bfloat16*)p_W5T, b5, gate);
    // scan as parallel reduction + output head
    scan_part<<<PB * 8, 256>>>(gate, (float*)p_pA, (float*)p_pB);
    scan_fin<<<PB, 256>>>((const float*)p_pA, (const float*)p_pB, Wo, bo, out);
}